// round 13
// baseline (speedup 1.0000x reference)
#include <cuda_runtime.h>

#define NB    32768
#define PP    32
#define NCC   33
#define IPB   32                    // items per block (4 lanes per item, 128 thr)
#define CHBLK (2 * NB / IPB)        // 2048 blocks: side = bid&1, ib = bid>>1

__device__ float g_partials[CHBLK];
__device__ int   g_count;           // zero-init; reset each launch by finisher

typedef unsigned long long ull;

__device__ __forceinline__ ull ffma2(ull a, ull b, ull c) {
    ull d; asm("fma.rn.f32x2 %0, %1, %2, %3;" : "=l"(d) : "l"(a), "l"(b), "l"(c)); return d;
}
__device__ __forceinline__ ull fadd2(ull a, ull b) {
    ull d; asm("add.rn.f32x2 %0, %1, %2;" : "=l"(d) : "l"(a), "l"(b)); return d;
}
__device__ __forceinline__ ull fmul2(ull a, ull b) {
    ull d; asm("mul.rn.f32x2 %0, %1, %2;" : "=l"(d) : "l"(a), "l"(b)); return d;
}
__device__ __forceinline__ ull pack2(float lo, float hi) {
    ull d; asm("mov.b64 %0, {%1, %2};" : "=l"(d) : "f"(lo), "f"(hi)); return d;
}
__device__ __forceinline__ float2 unpack2(ull v) {
    float2 r; asm("mov.b64 {%0, %1}, %2;" : "=f"(r.x), "=f"(r.y) : "l"(v)); return r;
}

// Local part of one pred-float4 body: distances vs this lane's 8 targets,
// local mins returned (butterflies done by the caller, batched).
__device__ __forceinline__ void body_local(float4 p, int i, int np,
                                           const ull* __restrict__ TX,
                                           const ull* __restrict__ TY,
                                           float* __restrict__ mintlo,
                                           float* __restrict__ minthi,
                                           float& sum_psq,
                                           float& mina, float& minb,
                                           bool& va, bool& vb) {
    va = (2 * i < np); vb = (2 * i + 1 < np);
    float ax = p.x, ay = p.y, bx = p.z, by = p.w;
    if (va) sum_psq += ax * ax + ay * ay; else { ax = -1e18f; ay = -1e18f; }
    if (vb) sum_psq += bx * bx + by * by; else { bx = -1e18f; by = -1e18f; }

    const ull AX = pack2(ax, ax), AY = pack2(ay, ay);
    const ull BX = pack2(bx, bx), BY = pack2(by, by);

    mina = 1e30f; minb = 1e30f;
#pragma unroll
    for (int j = 0; j < 4; j++) {
        ull dxa = fadd2(AX, TX[j]);
        ull dya = fadd2(AY, TY[j]);
        ull da  = ffma2(dxa, dxa, fmul2(dya, dya));
        ull dxb = fadd2(BX, TX[j]);
        ull dyb = fadd2(BY, TY[j]);
        ull db  = ffma2(dxb, dxb, fmul2(dyb, dyb));
        float2 daf = unpack2(da), dbf = unpack2(db);
        mina = fminf(mina, fminf(daf.x, daf.y));
        minb = fminf(minb, fminf(dbf.x, dbf.y));
        mintlo[j] = fminf(mintlo[j], fminf(daf.x, dbf.x));
        minthi[j] = fminf(minthi[j], fminf(daf.y, dbf.y));
    }
}

__global__ __launch_bounds__(128, 7)
void fused_kernel(const float*  __restrict__ pole_logits,
                  const float*  __restrict__ zero_logits,
                  const float4* __restrict__ poles,
                  const float4* __restrict__ zeros,
                  const float4* __restrict__ tpoles,
                  const float4* __restrict__ tzeros,
                  const int*    __restrict__ tnp,
                  const int*    __restrict__ tnz,
                  float*        __restrict__ out) {
    __shared__ __align__(16) float slog[IPB * NCC];   // 1056 floats = 4224 B
    __shared__ float sred[128];
    __shared__ int   sflag;

    const int tid  = threadIdx.x;
    const int side = blockIdx.x & 1;
    const int ib   = blockIdx.x >> 1;
    const int q    = tid & 3;           // lane within 4-group
    const int item = tid >> 2;          // 0..31
    const int b    = ib * IPB + item;

    const float*  logits = side ? zero_logits : pole_logits;
    const float4* pred   = (side ? zeros  : poles)  + (size_t)b * (PP / 2);
    const float4* tgt    = (side ? tzeros : tpoles) + (size_t)b * (PP / 2);
    const int*    tn     = side ? tnz : tnp;

    if (tid == 0) sflag = 0;

    // Stage this block's 32 logit rows (264 float4, coalesced, strided).
    {
        const float4* src = (const float4*)(logits + (size_t)ib * IPB * NCC);
        for (int i = tid; i < IPB * NCC / 4; i += 128)
            ((float4*)slog)[i] = __ldg(src + i);
    }
    __syncthreads();

    // ---- CE split across the 4-lane group: lane q handles classes q+4k ----
    const float* row = &slog[item * NCC];
    const int tc = __ldg(tn + b);

    float m = -1e30f; int amax = NCC - 1;
#pragma unroll
    for (int k = 0; k < 9; k++) {
        const int j = q + 4 * k;
        if (j < NCC) {
            float x = row[j];
            if (x > m) { m = x; amax = j; }
        }
    }
    // Exact first-occurrence argmax: larger value wins; tie -> smaller index.
#pragma unroll
    for (int st = 1; st < 4; st <<= 1) {
        float mx = __shfl_xor_sync(0xFFFFFFFFu, m, st);
        int   ix = __shfl_xor_sync(0xFFFFFFFFu, amax, st);
        if (mx > m || (mx == m && ix < amax)) { m = mx; amax = ix; }
    }
    float es = 0.f;
#pragma unroll
    for (int k = 0; k < 9; k++) {
        const int j = q + 4 * k;
        if (j < NCC) es += __expf(row[j] - m);
    }
#pragma unroll
    for (int st = 1; st < 4; st <<= 1)
        es += __shfl_xor_sync(0xFFFFFFFFu, es, st);
    const float ce = m + __logf(es) - row[tc];
    const int np = amax;     // identical on all 4 lanes
    const int nt = tc;

    // ---- Chamfer: lane q owns targets [8q, 8q+8) ----
    ull TX[4], TY[4];
    float sum_tsq_loc = 0.f;
#pragma unroll
    for (int j = 0; j < 4; j++) {
        float4 t = __ldg(tgt + 4 * q + j);
        const int g = 8 * q + 2 * j;
        float x0, y0, x1, y1;
        if (g < nt)     { sum_tsq_loc += t.x * t.x + t.y * t.y; x0 = -t.x; y0 = -t.y; }
        else            { x0 = -1e18f; y0 = -1e18f; }
        if (g + 1 < nt) { sum_tsq_loc += t.z * t.z + t.w * t.w; x1 = -t.z; y1 = -t.w; }
        else            { x1 = -1e18f; y1 = -1e18f; }
        TX[j] = pack2(x0, x1); TY[j] = pack2(y0, y1);
    }

    float mintlo[4], minthi[4];
#pragma unroll
    for (int j = 0; j < 4; j++) { mintlo[j] = 1e30f; minthi[j] = 1e30f; }

    float sum_minp = 0.f, sum_psq = 0.f;

    // Stream all 32 preds: 2 float4 loads batched at iteration top; the two
    // bodies' local mins computed first, then ALL butterflies issued together
    // (4 independent 2-step chains -> one overlapped SHFL-latency window).
#pragma unroll 1
    for (int c = 0; c < 8; c++) {
        float4 p0 = __ldg(pred + 2 * c + 0);
        float4 p1 = __ldg(pred + 2 * c + 1);

        float mina0, minb0, mina1, minb1;
        bool va0, vb0, va1, vb1;
        body_local(p0, 2 * c + 0, np, TX, TY, mintlo, minthi, sum_psq, mina0, minb0, va0, vb0);
        body_local(p1, 2 * c + 1, np, TX, TY, mintlo, minthi, sum_psq, mina1, minb1, va1, vb1);

        // Batched butterflies: all step-1s, then all step-2s.
        float sa0 = __shfl_xor_sync(0xFFFFFFFFu, mina0, 1);
        float sb0 = __shfl_xor_sync(0xFFFFFFFFu, minb0, 1);
        float sa1 = __shfl_xor_sync(0xFFFFFFFFu, mina1, 1);
        float sb1 = __shfl_xor_sync(0xFFFFFFFFu, minb1, 1);
        mina0 = fminf(mina0, sa0); minb0 = fminf(minb0, sb0);
        mina1 = fminf(mina1, sa1); minb1 = fminf(minb1, sb1);
        sa0 = __shfl_xor_sync(0xFFFFFFFFu, mina0, 2);
        sb0 = __shfl_xor_sync(0xFFFFFFFFu, minb0, 2);
        sa1 = __shfl_xor_sync(0xFFFFFFFFu, mina1, 2);
        sb1 = __shfl_xor_sync(0xFFFFFFFFu, minb1, 2);
        mina0 = fminf(mina0, sa0); minb0 = fminf(minb0, sb0);
        mina1 = fminf(mina1, sa1); minb1 = fminf(minb1, sb1);

        if (va0) sum_minp += mina0;
        if (vb0) sum_minp += minb0;
        if (va1) sum_minp += mina1;
        if (vb1) sum_minp += minb1;
    }

    float sum_mint_loc = 0.f;
#pragma unroll
    for (int j = 0; j < 4; j++) {
        const int g = 8 * q + 2 * j;
        if (g < nt)     sum_mint_loc += mintlo[j];
        if (g + 1 < nt) sum_mint_loc += minthi[j];
    }
    float sum_mint = sum_mint_loc + __shfl_xor_sync(0xFFFFFFFFu, sum_mint_loc, 1);
    sum_mint      += __shfl_xor_sync(0xFFFFFFFFu, sum_mint, 2);
    float sum_tsq  = sum_tsq_loc + __shfl_xor_sync(0xFFFFFFFFu, sum_tsq_loc, 1);
    sum_tsq       += __shfl_xor_sync(0xFFFFFFFFu, sum_tsq, 2);

    float ch;
    if (np == 0 && nt == 0) ch = 0.f;
    else if (np == 0)       ch = sum_tsq;
    else if (nt == 0)       ch = sum_psq;
    else                    ch = sum_minp / (float)np + sum_mint / (float)nt;

    float acc = (q == 0) ? (5.f * ce + ch) : 0.f;   // count each item once

    // Deterministic block tree reduction
    sred[tid] = acc;
    __syncthreads();
#pragma unroll
    for (int s = 64; s > 0; s >>= 1) {
        if (tid < s) sred[tid] += sred[tid + s];
        __syncthreads();
    }

    if (tid == 0) {
        g_partials[blockIdx.x] = sred[0];
        __threadfence();
        unsigned n = atomicAdd(&g_count, 1);
        if (n == CHBLK - 1) sflag = 1;
    }
    __syncthreads();

    // Last block: deterministic fixed-order sum over all 2048 partials.
    if (sflag) {
        __threadfence();
        volatile float* vp = g_partials;
        float t = 0.f;
#pragma unroll
        for (int k = 0; k < CHBLK / 128; k++)
            t += vp[tid + 128 * k];
        sred[tid] = t;
        __syncthreads();
#pragma unroll
        for (int s = 64; s > 0; s >>= 1) {
            if (tid < s) sred[tid] += sred[tid + s];
            __syncthreads();
        }
        if (tid == 0) {
            out[0] = sred[0] * (1.0f / (float)NB);
            g_count = 0;   // reset for next graph replay
        }
    }
}

extern "C" void kernel_launch(void* const* d_in, const int* in_sizes, int n_in,
                              void* d_out, int out_size) {
    const float*  pole_logits = (const float*)d_in[0];
    const float*  zero_logits = (const float*)d_in[1];
    const float4* poles       = (const float4*)d_in[2];
    const float4* zeros       = (const float4*)d_in[3];
    const float4* tpoles      = (const float4*)d_in[4];
    const float4* tzeros      = (const float4*)d_in[5];
    const int*    tnp         = (const int*)d_in[6];
    const int*    tnz         = (const int*)d_in[7];

    fused_kernel<<<CHBLK, 128>>>(pole_logits, zero_logits, poles, zeros,
                                 tpoles, tzeros, tnp, tnz, (float*)d_out);
}

// round 15
// speedup vs baseline: 1.1015x; 1.1015x over previous
#include <cuda_runtime.h>

#define NB    32768
#define PP    32
#define NCC   33
#define IPB   32                    // items per block (4 lanes per item, 128 thr)
#define CHBLK (2 * NB / IPB)        // 2048 blocks: side = bid&1, ib = bid>>1
#define PSTRIDE 17                  // float4 stride per item in spred (bank-spread)

__device__ float g_partials[CHBLK];
__device__ int   g_count;           // zero-init; reset each launch by finisher

typedef unsigned long long ull;

__device__ __forceinline__ ull ffma2(ull a, ull b, ull c) {
    ull d; asm("fma.rn.f32x2 %0, %1, %2, %3;" : "=l"(d) : "l"(a), "l"(b), "l"(c)); return d;
}
__device__ __forceinline__ ull fadd2(ull a, ull b) {
    ull d; asm("add.rn.f32x2 %0, %1, %2;" : "=l"(d) : "l"(a), "l"(b)); return d;
}
__device__ __forceinline__ ull fmul2(ull a, ull b) {
    ull d; asm("mul.rn.f32x2 %0, %1, %2;" : "=l"(d) : "l"(a), "l"(b)); return d;
}
__device__ __forceinline__ ull pack2(float lo, float hi) {
    ull d; asm("mov.b64 %0, {%1, %2};" : "=l"(d) : "f"(lo), "f"(hi)); return d;
}
__device__ __forceinline__ float2 unpack2(ull v) {
    float2 r; asm("mov.b64 {%0, %1}, %2;" : "=f"(r.x), "=f"(r.y) : "l"(v)); return r;
}

// Local part of one pred-float4 body: distances vs this lane's 8 targets
// (scalar FMNMX mins; min.f32x2 does not exist on sm_103a).
__device__ __forceinline__ void body_local(float4 p, int i, int np,
                                           const ull* __restrict__ TX,
                                           const ull* __restrict__ TY,
                                           float* __restrict__ mintlo,
                                           float* __restrict__ minthi,
                                           float& sum_psq,
                                           float& mina, float& minb,
                                           bool& va, bool& vb) {
    va = (2 * i < np); vb = (2 * i + 1 < np);
    float ax = p.x, ay = p.y, bx = p.z, by = p.w;
    if (va) sum_psq += ax * ax + ay * ay; else { ax = -1e18f; ay = -1e18f; }
    if (vb) sum_psq += bx * bx + by * by; else { bx = -1e18f; by = -1e18f; }

    const ull AX = pack2(ax, ax), AY = pack2(ay, ay);
    const ull BX = pack2(bx, bx), BY = pack2(by, by);

    mina = 1e30f; minb = 1e30f;
#pragma unroll
    for (int j = 0; j < 4; j++) {
        ull dxa = fadd2(AX, TX[j]);
        ull dya = fadd2(AY, TY[j]);
        ull da  = ffma2(dxa, dxa, fmul2(dya, dya));
        ull dxb = fadd2(BX, TX[j]);
        ull dyb = fadd2(BY, TY[j]);
        ull db  = ffma2(dxb, dxb, fmul2(dyb, dyb));
        float2 daf = unpack2(da), dbf = unpack2(db);
        mina = fminf(mina, fminf(daf.x, daf.y));
        minb = fminf(minb, fminf(dbf.x, dbf.y));
        mintlo[j] = fminf(mintlo[j], fminf(daf.x, dbf.x));
        minthi[j] = fminf(minthi[j], fminf(daf.y, dbf.y));
    }
}

__global__ __launch_bounds__(128, 7)
void fused_kernel(const float*  __restrict__ pole_logits,
                  const float*  __restrict__ zero_logits,
                  const float4* __restrict__ poles,
                  const float4* __restrict__ zeros,
                  const float4* __restrict__ tpoles,
                  const float4* __restrict__ tzeros,
                  const int*    __restrict__ tnp,
                  const int*    __restrict__ tnz,
                  float*        __restrict__ out) {
    __shared__ __align__(16) float slog[IPB * NCC];          // 4224 B
    __shared__ __align__(16) float4 spred[IPB * PSTRIDE];    // 8704 B
    __shared__ float sred[128];
    __shared__ int   sflag;

    const int tid  = threadIdx.x;
    const int side = blockIdx.x & 1;
    const int ib   = blockIdx.x >> 1;
    const int q    = tid & 3;           // lane within 4-group
    const int item = tid >> 2;          // 0..31
    const int b    = ib * IPB + item;

    const float*  logits = side ? zero_logits : pole_logits;
    const float4* gpred  = (side ? zeros  : poles)  + (size_t)ib * IPB * (PP / 2);
    const float4* tgt    = (side ? tzeros : tpoles) + (size_t)b * (PP / 2);
    const int*    tn     = side ? tnz : tnp;

    if (tid == 0) sflag = 0;

    // Stage logits (264 float4) and this block's pred tile (512 float4,
    // coalesced; smem layout padded to PSTRIDE float4 per item).
    {
        const float4* src = (const float4*)(logits + (size_t)ib * IPB * NCC);
        for (int i = tid; i < IPB * NCC / 4; i += 128)
            ((float4*)slog)[i] = __ldg(src + i);
#pragma unroll
        for (int k = 0; k < 4; k++) {
            const int i = tid + 128 * k;           // 0..511
            const int it = i >> 4, w = i & 15;
            spred[it * PSTRIDE + w] = __ldg(gpred + i);
        }
    }
    __syncthreads();

    // ---- CE split across the 4-lane group: lane q handles classes q+4k ----
    const float* row = &slog[item * NCC];
    const int tc = __ldg(tn + b);

    float m = -1e30f; int amax = NCC - 1;
#pragma unroll
    for (int k = 0; k < 9; k++) {
        const int j = q + 4 * k;
        if (j < NCC) {
            float x = row[j];
            if (x > m) { m = x; amax = j; }
        }
    }
#pragma unroll
    for (int st = 1; st < 4; st <<= 1) {
        float mx = __shfl_xor_sync(0xFFFFFFFFu, m, st);
        int   ix = __shfl_xor_sync(0xFFFFFFFFu, amax, st);
        if (mx > m || (mx == m && ix < amax)) { m = mx; amax = ix; }
    }
    float es = 0.f;
#pragma unroll
    for (int k = 0; k < 9; k++) {
        const int j = q + 4 * k;
        if (j < NCC) es += __expf(row[j] - m);
    }
#pragma unroll
    for (int st = 1; st < 4; st <<= 1)
        es += __shfl_xor_sync(0xFFFFFFFFu, es, st);
    const float ce = m + __logf(es) - row[tc];
    const int np = amax;     // identical on all 4 lanes
    const int nt = tc;

    // ---- Chamfer: lane q owns targets [8q, 8q+8) ----
    ull TX[4], TY[4];
    float sum_tsq_loc = 0.f;
#pragma unroll
    for (int j = 0; j < 4; j++) {
        float4 t = __ldg(tgt + 4 * q + j);
        const int g = 8 * q + 2 * j;
        float x0, y0, x1, y1;
        if (g < nt)     { sum_tsq_loc += t.x * t.x + t.y * t.y; x0 = -t.x; y0 = -t.y; }
        else            { x0 = -1e18f; y0 = -1e18f; }
        if (g + 1 < nt) { sum_tsq_loc += t.z * t.z + t.w * t.w; x1 = -t.z; y1 = -t.w; }
        else            { x1 = -1e18f; y1 = -1e18f; }
        TX[j] = pack2(x0, x1); TY[j] = pack2(y0, y1);
    }

    float mintlo[4], minthi[4];
#pragma unroll
    for (int j = 0; j < 4; j++) { mintlo[j] = 1e30f; minthi[j] = 1e30f; }

    float sum_minp = 0.f, sum_psq = 0.f;

    // Stream all 32 preds FROM SHARED MEMORY (broadcast across the 4-lane
    // group; PSTRIDE spreads items over banks -> conflict-free).
    const float4* mypred = &spred[item * PSTRIDE];
#pragma unroll 1
    for (int c = 0; c < 8; c++) {
        float4 p0 = mypred[2 * c + 0];
        float4 p1 = mypred[2 * c + 1];

        float mina0, minb0, mina1, minb1;
        bool va0, vb0, va1, vb1;
        body_local(p0, 2 * c + 0, np, TX, TY, mintlo, minthi, sum_psq, mina0, minb0, va0, vb0);
        body_local(p1, 2 * c + 1, np, TX, TY, mintlo, minthi, sum_psq, mina1, minb1, va1, vb1);

        // Batched butterflies: all step-1s, then all step-2s.
        float sa0 = __shfl_xor_sync(0xFFFFFFFFu, mina0, 1);
        float sb0 = __shfl_xor_sync(0xFFFFFFFFu, minb0, 1);
        float sa1 = __shfl_xor_sync(0xFFFFFFFFu, mina1, 1);
        float sb1 = __shfl_xor_sync(0xFFFFFFFFu, minb1, 1);
        mina0 = fminf(mina0, sa0); minb0 = fminf(minb0, sb0);
        mina1 = fminf(mina1, sa1); minb1 = fminf(minb1, sb1);
        sa0 = __shfl_xor_sync(0xFFFFFFFFu, mina0, 2);
        sb0 = __shfl_xor_sync(0xFFFFFFFFu, minb0, 2);
        sa1 = __shfl_xor_sync(0xFFFFFFFFu, mina1, 2);
        sb1 = __shfl_xor_sync(0xFFFFFFFFu, minb1, 2);
        mina0 = fminf(mina0, sa0); minb0 = fminf(minb0, sb0);
        mina1 = fminf(mina1, sa1); minb1 = fminf(minb1, sb1);

        if (va0) sum_minp += mina0;
        if (vb0) sum_minp += minb0;
        if (va1) sum_minp += mina1;
        if (vb1) sum_minp += minb1;
    }

    float sum_mint_loc = 0.f;
#pragma unroll
    for (int j = 0; j < 4; j++) {
        const int g = 8 * q + 2 * j;
        if (g < nt)     sum_mint_loc += mintlo[j];
        if (g + 1 < nt) sum_mint_loc += minthi[j];
    }
    float sum_mint = sum_mint_loc + __shfl_xor_sync(0xFFFFFFFFu, sum_mint_loc, 1);
    sum_mint      += __shfl_xor_sync(0xFFFFFFFFu, sum_mint, 2);
    float sum_tsq  = sum_tsq_loc + __shfl_xor_sync(0xFFFFFFFFu, sum_tsq_loc, 1);
    sum_tsq       += __shfl_xor_sync(0xFFFFFFFFu, sum_tsq, 2);

    float ch;
    if (np == 0 && nt == 0) ch = 0.f;
    else if (np == 0)       ch = sum_tsq;
    else if (nt == 0)       ch = sum_psq;
    else                    ch = sum_minp / (float)np + sum_mint / (float)nt;

    float acc = (q == 0) ? (5.f * ce + ch) : 0.f;   // count each item once

    // Deterministic block tree reduction
    sred[tid] = acc;
    __syncthreads();
#pragma unroll
    for (int s = 64; s > 0; s >>= 1) {
        if (tid < s) sred[tid] += sred[tid + s];
        __syncthreads();
    }

    if (tid == 0) {
        g_partials[blockIdx.x] = sred[0];
        __threadfence();
        unsigned n = atomicAdd(&g_count, 1);
        if (n == CHBLK - 1) sflag = 1;
    }
    __syncthreads();

    // Last block: deterministic fixed-order sum over all 2048 partials.
    if (sflag) {
        __threadfence();
        volatile float* vp = g_partials;
        float t = 0.f;
#pragma unroll
        for (int k = 0; k < CHBLK / 128; k++)
            t += vp[tid + 128 * k];
        sred[tid] = t;
        __syncthreads();
#pragma unroll
        for (int s = 64; s > 0; s >>= 1) {
            if (tid < s) sred[tid] += sred[tid + s];
            __syncthreads();
        }
        if (tid == 0) {
            out[0] = sred[0] * (1.0f / (float)NB);
            g_count = 0;   // reset for next graph replay
        }
    }
}

extern "C" void kernel_launch(void* const* d_in, const int* in_sizes, int n_in,
                              void* d_out, int out_size) {
    const float*  pole_logits = (const float*)d_in[0];
    const float*  zero_logits = (const float*)d_in[1];
    const float4* poles       = (const float4*)d_in[2];
    const float4* zeros       = (const float4*)d_in[3];
    const float4* tpoles      = (const float4*)d_in[4];
    const float4* tzeros      = (const float4*)d_in[5];
    const int*    tnp         = (const int*)d_in[6];
    const int*    tnz         = (const int*)d_in[7];

    fused_kernel<<<CHBLK, 128>>>(pole_logits, zero_logits, poles, zeros,
                                 tpoles, tzeros, tnp, tnz, (float*)d_out);
}